// round 16
// baseline (speedup 1.0000x reference)
#include <cuda_runtime.h>
#include <cstdint>

#define N_NODES 100000
#define N_EDGES 1600000
#define HC 128            // HEADS * OUT_CH
#define HEADS 4
#define OUT_CH 32
#define EDGE_CH 32
#define SCAN_BLK 1024
#define SCAN_NB ((N_NODES + SCAN_BLK - 1) / SCAN_BLK)   // 98
#define GEMM_BLOCKS 296
#define GEMM_SMEM ((128 * 33 + 32 * 33) * 16)           // 84480 bytes
#define LOG_BLK 256       // edges per logits block; N_EDGES % LOG_BLK == 0 (6250 blocks)

__constant__ float c_neg_slope = 0.2f;

// ---------------- scratch (static device globals; no allocation) ----------------
__device__ float  g_xl[(size_t)N_NODES * HC];   // 51.2 MB projected node features
__device__ float  g_al[N_NODES * HEADS];        // alpha_l per node/head
__device__ float  g_ar[N_NODES * HEADS];        // alpha_r per node/head
__device__ float  g_we[HC];                     // folded We^T * att_e  [H][32]
__device__ float4 g_denom[N_NODES];             // softmax denominators (sum of ex)
__device__ int    g_hist[N_NODES];              // in-degree histogram
__device__ int    g_offs[N_NODES];              // CSR start offsets (exclusive scan)
__device__ int    g_cursor[N_NODES];            // scatter cursors
__device__ int    g_bsum[SCAN_NB];              // scan block sums
__device__ int    g_csr_src[N_EDGES];           // dst-sorted source node ids
__device__ float4 g_csr_ex[N_EDGES];            // dst-sorted UNnormalized exp(logit)

// vectorized 16B global reduction (sm_90+)
__device__ __forceinline__ void red_add_v4(float4* p, float4 v) {
    asm volatile("red.global.add.v4.f32 [%0], {%1, %2, %3, %4};"
                 :: "l"(p), "f"(v.x), "f"(v.y), "f"(v.z), "f"(v.w)
                 : "memory");
}

// ---------------- zero hist + denom ----------------
__global__ void k_zero() {
    int idx = blockIdx.x * blockDim.x + threadIdx.x;
    if (idx < N_NODES * HEADS) ((float*)g_denom)[idx] = 0.0f;
    if (idx < N_NODES) g_hist[idx] = 0;
}

// ---------------- fold We with att_e  ->  g_we[h*32+k] ----------------
__global__ void k_wepre(const float* __restrict__ We, const float* __restrict__ att_e) {
    int t = threadIdx.x;           // 0..127  = h*32 + k
    int h = t >> 5, k = t & 31;
    float s = 0.0f;
#pragma unroll
    for (int c = 0; c < OUT_CH; c++)
        s += We[(h * OUT_CH + c) * EDGE_CH + k] * att_e[h * OUT_CH + c];
    g_we[t] = s;
}

// ---------------- in-degree histogram (dst only, int4 vectorized) ----------------
__global__ void k_hist(const int* __restrict__ ei) {
    int i = blockIdx.x * blockDim.x + threadIdx.x;   // quad index
    if (i * 4 >= N_EDGES) return;
    int4 d = ((const int4*)(ei + N_EDGES))[i];
    atomicAdd(&g_hist[d.x], 1);
    atomicAdd(&g_hist[d.y], 1);
    atomicAdd(&g_hist[d.z], 1);
    atomicAdd(&g_hist[d.w], 1);
}

// ---------------- register-blocked GEMM (R15 body, conflict-free) ----------------
__global__ __launch_bounds__(128, 2) void k_gemm(const float* __restrict__ x,
                                                 const float* __restrict__ Wl,
                                                 const float* __restrict__ att_l,
                                                 const float* __restrict__ att_r) {
    extern __shared__ float4 smem4[];
    float4* ws4 = smem4;                 // [128 cols][33]  (32 used + 1 pad)
    float4* xs4 = smem4 + 128 * 33;      // [32 nodes][33]

    const int tid      = threadIdx.x;
    const int lane     = tid & 31;
    const int w        = tid >> 5;       // warp index == head
    const int tc_local = lane >> 3;      // 0..3  (== LDS phase id)
    const int tn       = lane & 7;       // 0..7 (node within phase)
    const int tc       = w * 4 + tc_local;  // 0..15 (col group of 8)

    float attl[8], attr[8];
#pragma unroll
    for (int i = 0; i < 8; i++) {
        attl[i] = att_l[tc * 8 + i];
        attr[i] = att_r[tc * 8 + i];
    }

    for (int idx = tid; idx < 128 * 32; idx += 128) {
        int col = idx >> 5, kq = idx & 31;
        ws4[col * 33 + kq] = ((const float4*)Wl)[idx];
    }

    for (int base = blockIdx.x * 32; base < N_NODES; base += gridDim.x * 32) {
        __syncthreads();
        for (int idx = tid; idx < 32 * 32; idx += 128) {
            int nn = idx >> 5, kq = idx & 31;
            xs4[nn * 33 + kq] = ((const float4*)x)[(size_t)(base + nn) * 32 + kq];
        }
        __syncthreads();

        float acc[4][8];
#pragma unroll
        for (int n = 0; n < 4; n++)
#pragma unroll
            for (int i = 0; i < 8; i++) acc[n][i] = 0.f;

#pragma unroll 2
        for (int kq = 0; kq < 32; kq++) {
            float4 xv[4], wv[8];
#pragma unroll
            for (int n = 0; n < 4; n++) xv[n] = xs4[(n * 8 + tn) * 33 + kq];   // stride-1 rows
#pragma unroll
            for (int i = 0; i < 8; i++) wv[i] = ws4[(tc * 8 + i) * 33 + kq];   // phase broadcast
#pragma unroll
            for (int n = 0; n < 4; n++)
#pragma unroll
                for (int i = 0; i < 8; i++)
                    acc[n][i] += xv[n].x * wv[i].x + xv[n].y * wv[i].y
                               + xv[n].z * wv[i].z + xv[n].w * wv[i].w;
        }

#pragma unroll
        for (int n = 0; n < 4; n++) {
            int node = base + n * 8 + tn;
            float4 lo = make_float4(acc[n][0], acc[n][1], acc[n][2], acc[n][3]);
            float4 hi = make_float4(acc[n][4], acc[n][5], acc[n][6], acc[n][7]);
            ((float4*)g_xl)[(size_t)node * 32 + tc * 2]     = lo;
            ((float4*)g_xl)[(size_t)node * 32 + tc * 2 + 1] = hi;
            float pl = 0.f, pr = 0.f;
#pragma unroll
            for (int i = 0; i < 8; i++) {
                pl += acc[n][i] * attl[i];
                pr += acc[n][i] * attr[i];
            }
            pl += __shfl_down_sync(0xffffffffu, pl, 16);
            pl += __shfl_down_sync(0xffffffffu, pl, 8);
            pr += __shfl_down_sync(0xffffffffu, pr, 16);
            pr += __shfl_down_sync(0xffffffffu, pr, 8);
            if (tc_local == 0) {
                g_al[node * HEADS + w] = pl;
                g_ar[node * HEADS + w] = pr;
            }
        }
    }
}

// ---------------- scan kernels: exclusive prefix over g_hist -> g_offs ----------------
__global__ void k_scan1() {
    __shared__ int wsum[32];
    int i = blockIdx.x * SCAN_BLK + threadIdx.x;
    int lane = threadIdx.x & 31, wid = threadIdx.x >> 5;
    int v = (i < N_NODES) ? g_hist[i] : 0;
    int inc = v;
#pragma unroll
    for (int off = 1; off < 32; off <<= 1) {
        int t = __shfl_up_sync(0xffffffffu, inc, off);
        if (lane >= off) inc += t;
    }
    if (lane == 31) wsum[wid] = inc;
    __syncthreads();
    if (wid == 0) {
        int s = wsum[lane];
#pragma unroll
        for (int off = 1; off < 32; off <<= 1) {
            int t = __shfl_up_sync(0xffffffffu, s, off);
            if (lane >= off) s += t;
        }
        wsum[lane] = s;
    }
    __syncthreads();
    int base = (wid > 0) ? wsum[wid - 1] : 0;
    if (i < N_NODES) g_offs[i] = base + inc - v;
    if (threadIdx.x == SCAN_BLK - 1) g_bsum[blockIdx.x] = base + inc;
}

__global__ void k_scan2() {   // single block, scan SCAN_NB (=98) block totals, exclusive
    __shared__ int wsum[4];
    int lane = threadIdx.x & 31, wid = threadIdx.x >> 5;
    int v = (threadIdx.x < SCAN_NB) ? g_bsum[threadIdx.x] : 0;
    int inc = v;
#pragma unroll
    for (int off = 1; off < 32; off <<= 1) {
        int t = __shfl_up_sync(0xffffffffu, inc, off);
        if (lane >= off) inc += t;
    }
    if (lane == 31) wsum[wid] = inc;
    __syncthreads();
    int base = 0;
    for (int w = 0; w < wid; w++) base += wsum[w];
    if (threadIdx.x < SCAN_NB) g_bsum[threadIdx.x] = base + inc - v;
}

__global__ void k_scan3() {   // apply block offsets; init cursor = offs
    int i = blockIdx.x * SCAN_BLK + threadIdx.x;
    if (i < N_NODES) {
        int o = g_offs[i] + g_bsum[blockIdx.x];
        g_offs[i]   = o;
        g_cursor[i] = o;
    }
}

// ---------------- fused logits, SMEM-STAGED: coalesced row staging kills 32-wf LDGs ----------------
// cooperative load: 256 edge rows per block, fully coalesced (0.25 wf/edge vs 8).
// compute: thread-per-edge from stride-33 tile, bank (t+k)%32 -> conflict-free.
__global__ void k_logits(const float* __restrict__ edge_attr, const int* __restrict__ ei) {
    __shared__ float we_s[HC];
    __shared__ float tile[LOG_BLK][33];
    const int t = threadIdx.x;
    if (t < HC) we_s[t] = g_we[t];

    const int base = blockIdx.x * LOG_BLK;
    const int e    = base + t;
    // per-edge index loads + cursor slot + alpha gathers early (latency under staging+sync)
    int src = ei[e];
    int dst = ei[N_EDGES + e];
    int pos = atomicAdd(&g_cursor[dst], 1);
    float4 al = ((const float4*)g_al)[src];
    float4 ar = ((const float4*)g_ar)[dst];

    {   // cooperative coalesced staging: 2048 float4 per block
        const float4* __restrict__ src4 = (const float4*)(edge_attr + (size_t)base * EDGE_CH);
#pragma unroll
        for (int i = 0; i < 8; i++) {
            int g = t + i * LOG_BLK;
            float4 v = src4[g];
            int r = g >> 3, q = (g & 7) * 4;
            tile[r][q + 0] = v.x; tile[r][q + 1] = v.y;
            tile[r][q + 2] = v.z; tile[r][q + 3] = v.w;
        }
    }
    __syncthreads();

    const float* __restrict__ row = tile[t];
    float p0 = 0.f, p1 = 0.f, p2 = 0.f, p3 = 0.f;
#pragma unroll
    for (int k = 0; k < EDGE_CH; k++) {
        float v = row[k];                    // bank (t+k)%32: conflict-free
        p0 += v * we_s[k];
        p1 += v * we_s[32 + k];
        p2 += v * we_s[64 + k];
        p3 += v * we_s[96 + k];
    }
    float a0 = al.x + ar.x + p0;
    float a1 = al.y + ar.y + p1;
    float a2 = al.z + ar.z + p2;
    float a3 = al.w + ar.w + p3;
    a0 = (a0 > 0.f) ? a0 : c_neg_slope * a0;
    a1 = (a1 > 0.f) ? a1 : c_neg_slope * a1;
    a2 = (a2 > 0.f) ? a2 : c_neg_slope * a2;
    a3 = (a3 > 0.f) ? a3 : c_neg_slope * a3;
    float4 ex = make_float4(__expf(a0), __expf(a1), __expf(a2), __expf(a3));
    g_csr_src[pos] = src;
    g_csr_ex[pos]  = ex;
    red_add_v4(&g_denom[dst], ex);
}

// ---------------- gather aggregation: one warp per dst node (R4 body, fp32) ----------------
__global__ void k_agg(const float* __restrict__ bias, float* __restrict__ out) {
    const int lane = threadIdx.x & 31;
    const int h    = lane >> 3;                 // head owning this lane's float4
    int node = blockIdx.x * (blockDim.x >> 5) + (threadIdx.x >> 5);
    if (node >= N_NODES) return;

    int beg = g_offs[node];
    int end = g_cursor[node];                   // start + degree
    float4 acc = make_float4(0.f, 0.f, 0.f, 0.f);

    int pos = beg;
    for (; pos + 3 < end; pos += 4) {
        int s0 = g_csr_src[pos];
        int s1 = g_csr_src[pos + 1];
        int s2 = g_csr_src[pos + 2];
        int s3 = g_csr_src[pos + 3];
        float a0 = ((const float*)g_csr_ex)[(size_t)pos * 4 + h];
        float a1 = ((const float*)g_csr_ex)[(size_t)(pos + 1) * 4 + h];
        float a2 = ((const float*)g_csr_ex)[(size_t)(pos + 2) * 4 + h];
        float a3 = ((const float*)g_csr_ex)[(size_t)(pos + 3) * 4 + h];
        float4 v0 = ((const float4*)g_xl)[(size_t)s0 * 32 + lane];
        float4 v1 = ((const float4*)g_xl)[(size_t)s1 * 32 + lane];
        float4 v2 = ((const float4*)g_xl)[(size_t)s2 * 32 + lane];
        float4 v3 = ((const float4*)g_xl)[(size_t)s3 * 32 + lane];
        acc.x += a0 * v0.x + a1 * v1.x + a2 * v2.x + a3 * v3.x;
        acc.y += a0 * v0.y + a1 * v1.y + a2 * v2.y + a3 * v3.y;
        acc.z += a0 * v0.z + a1 * v1.z + a2 * v2.z + a3 * v3.z;
        acc.w += a0 * v0.w + a1 * v1.w + a2 * v2.w + a3 * v3.w;
    }
    for (; pos < end; pos++) {
        int s0 = g_csr_src[pos];
        float a0 = ((const float*)g_csr_ex)[(size_t)pos * 4 + h];
        float4 v0 = ((const float4*)g_xl)[(size_t)s0 * 32 + lane];
        acc.x += a0 * v0.x; acc.y += a0 * v0.y; acc.z += a0 * v0.z; acc.w += a0 * v0.w;
    }
    float inv = 1.0f / (((const float*)g_denom)[(size_t)node * 4 + h] + 1e-16f);
    float4 b = ((const float4*)bias)[lane];
    acc.x = acc.x * inv + b.x;
    acc.y = acc.y * inv + b.y;
    acc.z = acc.z * inv + b.z;
    acc.w = acc.w * inv + b.w;
    ((float4*)out)[(size_t)node * 32 + lane] = acc;
}

// ---------------- launch: R13 schedule; k_gemm in profile slot ----------------
extern "C" void kernel_launch(void* const* d_in, const int* in_sizes, int n_in,
                              void* d_out, int out_size) {
    const float* x         = (const float*)d_in[0];
    const float* edge_attr = (const float*)d_in[1];
    const float* Wl        = (const float*)d_in[2];
    const float* We        = (const float*)d_in[3];
    const float* att_l     = (const float*)d_in[4];
    const float* att_r     = (const float*)d_in[5];
    const float* att_e     = (const float*)d_in[6];
    const float* bias      = (const float*)d_in[7];
    const int*   ei        = (const int*)d_in[8];
    float* out = (float*)d_out;

    cudaFuncSetAttribute(k_gemm, cudaFuncAttributeMaxDynamicSharedMemorySize, GEMM_SMEM);

    cudaStream_t sA, sB;
    cudaStreamCreateWithFlags(&sA, cudaStreamNonBlocking);
    cudaStreamCreateWithFlags(&sB, cudaStreamNonBlocking);
    cudaEvent_t evRoot, evA, evB;
    cudaEventCreateWithFlags(&evRoot, cudaEventDisableTiming);
    cudaEventCreateWithFlags(&evA,    cudaEventDisableTiming);
    cudaEventCreateWithFlags(&evB,    cudaEventDisableTiming);

    cudaEventRecord(evRoot, 0);
    cudaStreamWaitEvent(sA, evRoot, 0);
    cudaStreamWaitEvent(sB, evRoot, 0);

    // Branch A part 1 (sA): launches 0-2
    k_zero <<<(N_NODES * HEADS + 255) / 256, 256, 0, sA>>>();
    k_hist <<<(N_EDGES / 4 + 255) / 256, 256, 0, sA>>>(ei);
    k_scan1<<<SCAN_NB, SCAN_BLK, 0, sA>>>();

    // Main stream: GEMM enqueued 4th -> ncu capture slot
    k_gemm<<<GEMM_BLOCKS, 128, GEMM_SMEM>>>(x, Wl, att_l, att_r);

    // Branch A part 2 (sA)
    k_scan2<<<1, 128, 0, sA>>>();
    k_scan3<<<SCAN_NB, SCAN_BLK, 0, sA>>>();
    cudaEventRecord(evA, sA);

    // Branch B (sB): tiny weight fold
    k_wepre<<<1, 128, 0, sB>>>(We, att_e);
    cudaEventRecord(evB, sB);

    // join
    cudaStreamWaitEvent(0, evA, 0);
    cudaStreamWaitEvent(0, evB, 0);

    k_logits<<<N_EDGES / LOG_BLK, LOG_BLK>>>(edge_attr, ei);
    k_agg<<<(N_NODES * 32 + 255) / 256, 256>>>(bias, out);

    cudaEventDestroy(evRoot);
    cudaEventDestroy(evA);
    cudaEventDestroy(evB);
    cudaStreamDestroy(sA);
    cudaStreamDestroy(sB);
}

// round 17
// speedup vs baseline: 1.1258x; 1.1258x over previous
#include <cuda_runtime.h>
#include <cstdint>

#define N_NODES 100000
#define N_EDGES 1600000
#define HC 128            // HEADS * OUT_CH
#define HEADS 4
#define OUT_CH 32
#define EDGE_CH 32
#define SCAN_BLK 1024
#define SCAN_NB ((N_NODES + SCAN_BLK - 1) / SCAN_BLK)   // 98
#define GEMM_BLOCKS 296
#define GEMM_SMEM ((128 * 33 + 32 * 33) * 16)           // 84480 bytes

__constant__ float c_neg_slope = 0.2f;

// ---------------- scratch (static device globals; no allocation) ----------------
__device__ float  g_xl[(size_t)N_NODES * HC];   // 51.2 MB projected node features
__device__ float  g_al[N_NODES * HEADS];        // alpha_l per node/head
__device__ float  g_ar[N_NODES * HEADS];        // alpha_r per node/head
__device__ float  g_we[HC];                     // folded We^T * att_e  [H][32]
__device__ float  g_ulr[8 * HC];                // folded Wl^T*att_l (rows 0-3) / att_r (4-7)
__device__ float4 g_denom[N_NODES];             // softmax denominators (sum of ex)
__device__ int    g_hist[N_NODES];              // in-degree histogram
__device__ int    g_offs[N_NODES];              // CSR start offsets (exclusive scan)
__device__ int    g_cursor[N_NODES];            // scatter cursors
__device__ int    g_bsum[SCAN_NB];              // scan block sums
__device__ int    g_csr_src[N_EDGES];           // dst-sorted source node ids
__device__ float4 g_csr_ex[N_EDGES];            // dst-sorted UNnormalized exp(logit)

// vectorized 16B global reduction (sm_90+)
__device__ __forceinline__ void red_add_v4(float4* p, float4 v) {
    asm volatile("red.global.add.v4.f32 [%0], {%1, %2, %3, %4};"
                 :: "l"(p), "f"(v.x), "f"(v.y), "f"(v.z), "f"(v.w)
                 : "memory");
}

// ---------------- zero hist + denom ----------------
__global__ void k_zero() {
    int idx = blockIdx.x * blockDim.x + threadIdx.x;
    if (idx < N_NODES * HEADS) ((float*)g_denom)[idx] = 0.0f;
    if (idx < N_NODES) g_hist[idx] = 0;
}

// ---------------- fold We*att_e AND Wl*att_l / Wl*att_r (one block, 128 threads) ----------------
__global__ void k_fold(const float* __restrict__ Wl, const float* __restrict__ We,
                       const float* __restrict__ att_l, const float* __restrict__ att_r,
                       const float* __restrict__ att_e) {
    int t = threadIdx.x;            // 0..127
    {   // We fold: t = h*32 + k
        int h = t >> 5, k = t & 31;
        float s = 0.0f;
#pragma unroll
        for (int c = 0; c < OUT_CH; c++)
            s += We[(h * OUT_CH + c) * EDGE_CH + k] * att_e[h * OUT_CH + c];
        g_we[t] = s;
    }
    {   // Wl folds: t = input channel k
#pragma unroll
        for (int h = 0; h < HEADS; h++) {
            float sl = 0.0f, sr = 0.0f;
#pragma unroll
            for (int c = 0; c < OUT_CH; c++) {
                float w = Wl[(size_t)(h * OUT_CH + c) * HC + t];
                sl += w * att_l[h * OUT_CH + c];
                sr += w * att_r[h * OUT_CH + c];
            }
            g_ulr[h * HC + t]           = sl;
            g_ulr[(HEADS + h) * HC + t] = sr;
        }
    }
}

// ---------------- alpha_l / alpha_r directly from x (no xl dependency; R10-validated) ----------------
__global__ void k_alphas(const float* __restrict__ x) {
    __shared__ float us[8 * HC];
    for (int i = threadIdx.x; i < 8 * HC; i += blockDim.x) us[i] = g_ulr[i];
    __syncthreads();

    int sub  = threadIdx.x & 7;
    int node = blockIdx.x * (blockDim.x >> 3) + (threadIdx.x >> 3);
    if (node >= N_NODES) return;

    const float4* __restrict__ row = (const float4*)(x + (size_t)node * HC);
    float p[8];
#pragma unroll
    for (int j = 0; j < 8; j++) p[j] = 0.f;
#pragma unroll
    for (int i = 0; i < 4; i++) {
        int c4 = sub + 8 * i;
        float4 xv = row[c4];
#pragma unroll
        for (int j = 0; j < 8; j++) {
            float4 uv = ((const float4*)us)[j * 32 + c4];
            p[j] += xv.x * uv.x + xv.y * uv.y + xv.z * uv.z + xv.w * uv.w;
        }
    }
#pragma unroll
    for (int off = 4; off; off >>= 1)
#pragma unroll
        for (int j = 0; j < 8; j++)
            p[j] += __shfl_down_sync(0xffffffffu, p[j], off, 8);
    if (sub == 0) {
        ((float4*)g_al)[node] = make_float4(p[0], p[1], p[2], p[3]);
        ((float4*)g_ar)[node] = make_float4(p[4], p[5], p[6], p[7]);
    }
}

// ---------------- in-degree histogram (dst only, int4 vectorized) ----------------
__global__ void k_hist(const int* __restrict__ ei) {
    int i = blockIdx.x * blockDim.x + threadIdx.x;   // quad index
    if (i * 4 >= N_EDGES) return;
    int4 d = ((const int4*)(ei + N_EDGES))[i];
    atomicAdd(&g_hist[d.x], 1);
    atomicAdd(&g_hist[d.y], 1);
    atomicAdd(&g_hist[d.z], 1);
    atomicAdd(&g_hist[d.w], 1);
}

// ---------------- register-blocked GEMM (R15 body, conflict-free; alpha epilogue REMOVED) ----------------
__global__ __launch_bounds__(128, 2) void k_gemm(const float* __restrict__ x,
                                                 const float* __restrict__ Wl) {
    extern __shared__ float4 smem4[];
    float4* ws4 = smem4;                 // [128 cols][33]  (32 used + 1 pad)
    float4* xs4 = smem4 + 128 * 33;      // [32 nodes][33]

    const int tid      = threadIdx.x;
    const int lane     = tid & 31;
    const int w        = tid >> 5;
    const int tc_local = lane >> 3;      // 0..3  (== LDS phase id)
    const int tn       = lane & 7;       // 0..7 (node within phase)
    const int tc       = w * 4 + tc_local;  // 0..15 (col group of 8)

    for (int idx = tid; idx < 128 * 32; idx += 128) {
        int col = idx >> 5, kq = idx & 31;
        ws4[col * 33 + kq] = ((const float4*)Wl)[idx];
    }

    for (int base = blockIdx.x * 32; base < N_NODES; base += gridDim.x * 32) {
        __syncthreads();
        for (int idx = tid; idx < 32 * 32; idx += 128) {
            int nn = idx >> 5, kq = idx & 31;
            xs4[nn * 33 + kq] = ((const float4*)x)[(size_t)(base + nn) * 32 + kq];
        }
        __syncthreads();

        float acc[4][8];
#pragma unroll
        for (int n = 0; n < 4; n++)
#pragma unroll
            for (int i = 0; i < 8; i++) acc[n][i] = 0.f;

#pragma unroll 2
        for (int kq = 0; kq < 32; kq++) {
            float4 xv[4], wv[8];
#pragma unroll
            for (int n = 0; n < 4; n++) xv[n] = xs4[(n * 8 + tn) * 33 + kq];   // stride-1 rows
#pragma unroll
            for (int i = 0; i < 8; i++) wv[i] = ws4[(tc * 8 + i) * 33 + kq];   // phase broadcast
#pragma unroll
            for (int n = 0; n < 4; n++)
#pragma unroll
                for (int i = 0; i < 8; i++)
                    acc[n][i] += xv[n].x * wv[i].x + xv[n].y * wv[i].y
                               + xv[n].z * wv[i].z + xv[n].w * wv[i].w;
        }

#pragma unroll
        for (int n = 0; n < 4; n++) {
            int node = base + n * 8 + tn;
            ((float4*)g_xl)[(size_t)node * 32 + tc * 2] =
                make_float4(acc[n][0], acc[n][1], acc[n][2], acc[n][3]);
            ((float4*)g_xl)[(size_t)node * 32 + tc * 2 + 1] =
                make_float4(acc[n][4], acc[n][5], acc[n][6], acc[n][7]);
        }
    }
}

// ---------------- scan kernels: exclusive prefix over g_hist -> g_offs ----------------
__global__ void k_scan1() {
    __shared__ int wsum[32];
    int i = blockIdx.x * SCAN_BLK + threadIdx.x;
    int lane = threadIdx.x & 31, wid = threadIdx.x >> 5;
    int v = (i < N_NODES) ? g_hist[i] : 0;
    int inc = v;
#pragma unroll
    for (int off = 1; off < 32; off <<= 1) {
        int t = __shfl_up_sync(0xffffffffu, inc, off);
        if (lane >= off) inc += t;
    }
    if (lane == 31) wsum[wid] = inc;
    __syncthreads();
    if (wid == 0) {
        int s = wsum[lane];
#pragma unroll
        for (int off = 1; off < 32; off <<= 1) {
            int t = __shfl_up_sync(0xffffffffu, s, off);
            if (lane >= off) s += t;
        }
        wsum[lane] = s;
    }
    __syncthreads();
    int base = (wid > 0) ? wsum[wid - 1] : 0;
    if (i < N_NODES) g_offs[i] = base + inc - v;
    if (threadIdx.x == SCAN_BLK - 1) g_bsum[blockIdx.x] = base + inc;
}

__global__ void k_scan2() {   // single block, scan SCAN_NB (=98) block totals, exclusive
    __shared__ int wsum[4];
    int lane = threadIdx.x & 31, wid = threadIdx.x >> 5;
    int v = (threadIdx.x < SCAN_NB) ? g_bsum[threadIdx.x] : 0;
    int inc = v;
#pragma unroll
    for (int off = 1; off < 32; off <<= 1) {
        int t = __shfl_up_sync(0xffffffffu, inc, off);
        if (lane >= off) inc += t;
    }
    if (lane == 31) wsum[wid] = inc;
    __syncthreads();
    int base = 0;
    for (int w = 0; w < wid; w++) base += wsum[w];
    if (threadIdx.x < SCAN_NB) g_bsum[threadIdx.x] = base + inc - v;
}

__global__ void k_scan3() {   // apply block offsets; init cursor = offs
    int i = blockIdx.x * SCAN_BLK + threadIdx.x;
    if (i < N_NODES) {
        int o = g_offs[i] + g_bsum[blockIdx.x];
        g_offs[i]   = o;
        g_cursor[i] = o;
    }
}

// ---------------- fused logits: thread-per-edge (282.8µs-validated body) ----------------
__global__ void k_logits(const float* __restrict__ edge_attr, const int* __restrict__ ei) {
    __shared__ float we_s[HC];
    if (threadIdx.x < HC) we_s[threadIdx.x] = g_we[threadIdx.x];
    __syncthreads();

    int e = blockIdx.x * blockDim.x + threadIdx.x;
    if (e >= N_EDGES) return;

    // hoisted: slot reservation + alpha gathers issue before the dot-product chain
    int src = ei[e];
    int dst = ei[N_EDGES + e];
    int pos = atomicAdd(&g_cursor[dst], 1);
    float4 al = ((const float4*)g_al)[src];
    float4 ar = ((const float4*)g_ar)[dst];

    const float4* __restrict__ row = (const float4*)(edge_attr + (size_t)e * EDGE_CH);
    const float4* w0 = (const float4*)(we_s);
    const float4* w1 = (const float4*)(we_s + 32);
    const float4* w2 = (const float4*)(we_s + 64);
    const float4* w3 = (const float4*)(we_s + 96);
    float p0 = 0.f, p1 = 0.f, p2 = 0.f, p3 = 0.f;
#pragma unroll
    for (int i = 0; i < 8; i++) {
        float4 v = row[i];
        float4 a0 = w0[i], a1 = w1[i], a2 = w2[i], a3 = w3[i];
        p0 += v.x * a0.x + v.y * a0.y + v.z * a0.z + v.w * a0.w;
        p1 += v.x * a1.x + v.y * a1.y + v.z * a1.z + v.w * a1.w;
        p2 += v.x * a2.x + v.y * a2.y + v.z * a2.z + v.w * a2.w;
        p3 += v.x * a3.x + v.y * a3.y + v.z * a3.z + v.w * a3.w;
    }
    float a0 = al.x + ar.x + p0;
    float a1 = al.y + ar.y + p1;
    float a2 = al.z + ar.z + p2;
    float a3 = al.w + ar.w + p3;
    a0 = (a0 > 0.f) ? a0 : c_neg_slope * a0;
    a1 = (a1 > 0.f) ? a1 : c_neg_slope * a1;
    a2 = (a2 > 0.f) ? a2 : c_neg_slope * a2;
    a3 = (a3 > 0.f) ? a3 : c_neg_slope * a3;
    float4 ex = make_float4(__expf(a0), __expf(a1), __expf(a2), __expf(a3));
    g_csr_src[pos] = src;
    g_csr_ex[pos]  = ex;
    red_add_v4(&g_denom[dst], ex);
}

// ---------------- gather aggregation: one warp per dst node (R4 body, fp32) ----------------
__global__ void k_agg(const float* __restrict__ bias, float* __restrict__ out) {
    const int lane = threadIdx.x & 31;
    const int h    = lane >> 3;                 // head owning this lane's float4
    int node = blockIdx.x * (blockDim.x >> 5) + (threadIdx.x >> 5);
    if (node >= N_NODES) return;

    int beg = g_offs[node];
    int end = g_cursor[node];                   // start + degree
    float4 acc = make_float4(0.f, 0.f, 0.f, 0.f);

    int pos = beg;
    for (; pos + 3 < end; pos += 4) {
        int s0 = g_csr_src[pos];
        int s1 = g_csr_src[pos + 1];
        int s2 = g_csr_src[pos + 2];
        int s3 = g_csr_src[pos + 3];
        float a0 = ((const float*)g_csr_ex)[(size_t)pos * 4 + h];
        float a1 = ((const float*)g_csr_ex)[(size_t)(pos + 1) * 4 + h];
        float a2 = ((const float*)g_csr_ex)[(size_t)(pos + 2) * 4 + h];
        float a3 = ((const float*)g_csr_ex)[(size_t)(pos + 3) * 4 + h];
        float4 v0 = ((const float4*)g_xl)[(size_t)s0 * 32 + lane];
        float4 v1 = ((const float4*)g_xl)[(size_t)s1 * 32 + lane];
        float4 v2 = ((const float4*)g_xl)[(size_t)s2 * 32 + lane];
        float4 v3 = ((const float4*)g_xl)[(size_t)s3 * 32 + lane];
        acc.x += a0 * v0.x + a1 * v1.x + a2 * v2.x + a3 * v3.x;
        acc.y += a0 * v0.y + a1 * v1.y + a2 * v2.y + a3 * v3.y;
        acc.z += a0 * v0.z + a1 * v1.z + a2 * v2.z + a3 * v3.z;
        acc.w += a0 * v0.w + a1 * v1.w + a2 * v2.w + a3 * v3.w;
    }
    for (; pos < end; pos++) {
        int s0 = g_csr_src[pos];
        float a0 = ((const float*)g_csr_ex)[(size_t)pos * 4 + h];
        float4 v0 = ((const float4*)g_xl)[(size_t)s0 * 32 + lane];
        acc.x += a0 * v0.x; acc.y += a0 * v0.y; acc.z += a0 * v0.z; acc.w += a0 * v0.w;
    }
    float inv = 1.0f / (((const float*)g_denom)[(size_t)node * 4 + h] + 1e-16f);
    float4 b = ((const float4*)bias)[lane];
    acc.x = acc.x * inv + b.x;
    acc.y = acc.y * inv + b.y;
    acc.z = acc.z * inv + b.z;
    acc.w = acc.w * inv + b.w;
    ((float4*)out)[(size_t)node * 32 + lane] = acc;
}

// ---------------- launch: gemm (sB) overlaps scans AND logits; alphas decoupled ----------------
extern "C" void kernel_launch(void* const* d_in, const int* in_sizes, int n_in,
                              void* d_out, int out_size) {
    const float* x         = (const float*)d_in[0];
    const float* edge_attr = (const float*)d_in[1];
    const float* Wl        = (const float*)d_in[2];
    const float* We        = (const float*)d_in[3];
    const float* att_l     = (const float*)d_in[4];
    const float* att_r     = (const float*)d_in[5];
    const float* att_e     = (const float*)d_in[6];
    const float* bias      = (const float*)d_in[7];
    const int*   ei        = (const int*)d_in[8];
    float* out = (float*)d_out;

    cudaFuncSetAttribute(k_gemm, cudaFuncAttributeMaxDynamicSharedMemorySize, GEMM_SMEM);

    cudaStream_t sA, sB;
    cudaStreamCreateWithFlags(&sA, cudaStreamNonBlocking);
    cudaStreamCreateWithFlags(&sB, cudaStreamNonBlocking);
    cudaEvent_t evRoot, evA, evB;
    cudaEventCreateWithFlags(&evRoot, cudaEventDisableTiming);
    cudaEventCreateWithFlags(&evA,    cudaEventDisableTiming);
    cudaEventCreateWithFlags(&evB,    cudaEventDisableTiming);

    cudaEventRecord(evRoot, 0);
    cudaStreamWaitEvent(sA, evRoot, 0);
    cudaStreamWaitEvent(sB, evRoot, 0);

    // Branch A part 1 (sA): edge-prep chain
    k_zero <<<(N_NODES * HEADS + 255) / 256, 256, 0, sA>>>();
    k_hist <<<(N_EDGES / 4 + 255) / 256, 256, 0, sA>>>(ei);
    k_scan1<<<SCAN_NB, SCAN_BLK, 0, sA>>>();

    // Branch B (sB): stripped GEMM, enqueued 4th -> ncu capture slot.
    // FMA/LDS-bound now, so it co-runs with the DRAM-bound logits below.
    k_gemm<<<GEMM_BLOCKS, 128, GEMM_SMEM, sB>>>(x, Wl);
    cudaEventRecord(evB, sB);

    // Branch A part 2 (sA)
    k_scan2<<<1, 128, 0, sA>>>();
    k_scan3<<<SCAN_NB, SCAN_BLK, 0, sA>>>();
    cudaEventRecord(evA, sA);

    // Main: folds -> alphas (both independent of gemm) -> logits (|| gemm) -> agg
    k_fold<<<1, 128>>>(Wl, We, att_l, att_r, att_e);
    k_alphas<<<(N_NODES * 8 + 255) / 256, 256>>>(x);
    cudaStreamWaitEvent(0, evA, 0);
    k_logits<<<(N_EDGES + 255) / 256, 256>>>(edge_attr, ei);
    cudaStreamWaitEvent(0, evB, 0);
    k_agg<<<(N_NODES * 32 + 255) / 256, 256>>>(bias, out);

    cudaEventDestroy(evRoot);
    cudaEventDestroy(evA);
    cudaEventDestroy(evB);
    cudaStreamDestroy(sA);
    cudaStreamDestroy(sB);
}